// round 16
// baseline (speedup 1.0000x reference)
#include <cuda_runtime.h>

#define BATCH 4
#define NQ    2048
#define NK    2048
#define DQ    1024
#define NH    8
#define HD    64
#define INNER 512
#define KKEEP 64
#define CCAP  512

// Scratch (device globals; allocation-free contract)
__device__ float g_Q [BATCH * NQ * INNER];          // 16.8 MB
__device__ float g_KV[BATCH * NK * 2 * INNER];      // 33.5 MB  (K: cols 0..511, V: 512..1023)
__device__ float g_S [134217728];                   // 512 MB   sim [B*H][NQ][NK]
__device__ float g_O [BATCH * NQ * INNER];          // 16.8 MB

// ---- tf32 split helpers + warp MMA --------------------------------------------
__device__ __forceinline__ void split_tf32(float v, unsigned& hi, unsigned& lo) {
    asm("cvt.rna.tf32.f32 %0, %1;" : "=r"(hi) : "f"(v));
    float l = v - __uint_as_float(hi);
    asm("cvt.rna.tf32.f32 %0, %1;" : "=r"(lo) : "f"(l));
}

#define MMA_TF32(c, a, b0, b1) \
    asm("mma.sync.aligned.m16n8k8.row.col.f32.tf32.tf32.f32 " \
        "{%0,%1,%2,%3}, {%4,%5,%6,%7}, {%8,%9}, {%0,%1,%2,%3};" \
        : "+f"((c)[0]), "+f"((c)[1]), "+f"((c)[2]), "+f"((c)[3]) \
        : "r"((a)[0]), "r"((a)[1]), "r"((a)[2]), "r"((a)[3]), "r"(b0), "r"(b1))

__device__ __forceinline__ unsigned fkey(float f) {
    unsigned u = __float_as_uint(f);
    return (u & 0x80000000u) ? ~u : (u | 0x80000000u);
}
__device__ __forceinline__ float unfkey(unsigned k) {
    unsigned u = (k & 0x80000000u) ? (k & 0x7fffffffu) : ~k;
    return __uint_as_float(u);
}

// ---------------------------------------------------------------------------
// fp32 SGEMM body (NN), double-buffered (bitwise-identical to prior rounds).
// ---------------------------------------------------------------------------
__device__ __forceinline__ void sgemm_body(
    float* smem, int bxx, int byy,
    const float* __restrict__ A, const float* __restrict__ Bm,
    float* __restrict__ C, int K, int lda, int ldb, int ldc)
{
    float (*As)[8][128] = (float (*)[8][128])smem;
    float (*Bs)[8][128] = (float (*)[8][128])(smem + 2048);
    const int tid  = threadIdx.x;
    const int row0 = byy * 128, col0 = bxx * 128;
    const int tx   = tid & 15, ty = tid >> 4;
    const int a_row = tid >> 1, a_k = (tid & 1) * 4;
    const int b_k   = tid >> 5, b_col = (tid & 31) * 4;
    const float* Ap = A  + (size_t)(row0 + a_row) * lda + a_k;
    const float* Bp = Bm + (size_t)b_k * ldb + col0 + b_col;

    float acc[8][8];
#pragma unroll
    for (int i = 0; i < 8; i++)
#pragma unroll
        for (int j = 0; j < 8; j++) acc[i][j] = 0.f;

    {
        float4 av = *(const float4*)Ap;
        float4 bv = *(const float4*)Bp;
        As[0][a_k + 0][a_row] = av.x;
        As[0][a_k + 1][a_row] = av.y;
        As[0][a_k + 2][a_row] = av.z;
        As[0][a_k + 3][a_row] = av.w;
        *(float4*)&Bs[0][b_k][b_col] = bv;
    }
    __syncthreads();

    int buf = 0;
    for (int k0 = 8; k0 <= K; k0 += 8) {
        const bool has = (k0 < K);
        float4 av, bv;
        if (has) {
            av = *(const float4*)(Ap + k0);
            bv = *(const float4*)(Bp + (size_t)k0 * ldb);
        }
#pragma unroll
        for (int kk = 0; kk < 8; kk++) {
            float af[8], bf[8];
            *(float4*)&af[0] = *(const float4*)&As[buf][kk][ty * 4];
            *(float4*)&af[4] = *(const float4*)&As[buf][kk][ty * 4 + 64];
            *(float4*)&bf[0] = *(const float4*)&Bs[buf][kk][tx * 4];
            *(float4*)&bf[4] = *(const float4*)&Bs[buf][kk][tx * 4 + 64];
#pragma unroll
            for (int i = 0; i < 8; i++)
#pragma unroll
                for (int j = 0; j < 8; j++)
                    acc[i][j] += af[i] * bf[j];
        }
        if (has) {
            const int nb = buf ^ 1;
            As[nb][a_k + 0][a_row] = av.x;
            As[nb][a_k + 1][a_row] = av.y;
            As[nb][a_k + 2][a_row] = av.z;
            As[nb][a_k + 3][a_row] = av.w;
            *(float4*)&Bs[nb][b_k][b_col] = bv;
            __syncthreads();
            buf = nb;
        }
    }

#pragma unroll
    for (int ih = 0; ih < 2; ih++)
#pragma unroll
        for (int ii = 0; ii < 4; ii++) {
            int row = row0 + ty * 4 + ih * 64 + ii;
            float* Cp = C + (size_t)row * ldc + col0;
#pragma unroll
            for (int jh = 0; jh < 2; jh++) {
                int c = tx * 4 + jh * 64;
                float4 v;
                v.x = acc[ih * 4 + ii][jh * 4 + 0];
                v.y = acc[ih * 4 + ii][jh * 4 + 1];
                v.z = acc[ih * 4 + ii][jh * 4 + 2];
                v.w = acc[ih * 4 + ii][jh * 4 + 3];
                *(float4*)(Cp + c) = v;
            }
        }
}

// ---------------------------------------------------------------------------
// 3xTF32 MMA GEMM body (NN), 256 threads (used only by V-proj in proj_fused).
// ---------------------------------------------------------------------------
__device__ __forceinline__ void tf32gemm_body(
    float* smem, int bxx, int byy,
    const float* __restrict__ A, const float* __restrict__ Bm,
    const float* __restrict__ bias, float* __restrict__ C,
    int K, int lda, int ldb, int ldc)
{
    float (*As)[128 * 12] = (float (*)[128 * 12])smem;
    float (*Bs)[128 * 12] = (float (*)[128 * 12])(smem + 2 * 128 * 12);
    const int tid  = threadIdx.x;
    const int row0 = byy * 128, col0 = bxx * 128;
    const int a_row = tid >> 1, a_k = (tid & 1) * 4;
    const int b_k   = tid >> 5, b_n = (tid & 31) * 4;
    const float* Ap = A  + (size_t)(row0 + a_row) * lda + a_k;
    const float* Bp = Bm + (size_t)b_k * ldb + col0 + b_n;

    {
        float4 a4 = *(const float4*)Ap;
        *(float4*)(As[0] + a_row * 12 + a_k) = a4;
        float4 b4 = *(const float4*)Bp;
        Bs[0][(b_n + 0) * 12 + b_k] = b4.x;
        Bs[0][(b_n + 1) * 12 + b_k] = b4.y;
        Bs[0][(b_n + 2) * 12 + b_k] = b4.z;
        Bs[0][(b_n + 3) * 12 + b_k] = b4.w;
    }
    __syncthreads();

    const int lane = tid & 31, wid = tid >> 5;
    const int wm = (wid & 3) * 32, wn = (wid >> 2) * 64;
    const int gr = lane >> 2, gc = lane & 3;

    float acc[2][8][4];
#pragma unroll
    for (int mi = 0; mi < 2; mi++)
#pragma unroll
        for (int ni = 0; ni < 8; ni++)
#pragma unroll
            for (int q = 0; q < 4; q++) acc[mi][ni][q] = 0.f;

    int buf = 0;
    for (int k0 = 8; k0 <= K; k0 += 8) {
        const bool has = (k0 < K);
        float4 a4, b4;
        if (has) {
            a4 = *(const float4*)(Ap + k0);
            b4 = *(const float4*)(Bp + (size_t)k0 * ldb);
        }
        unsigned ahi[2][4], alo[2][4];
#pragma unroll
        for (int mi = 0; mi < 2; mi++) {
            int m = wm + mi * 16 + gr;
            split_tf32(As[buf][m * 12 + gc],           ahi[mi][0], alo[mi][0]);
            split_tf32(As[buf][(m + 8) * 12 + gc],     ahi[mi][1], alo[mi][1]);
            split_tf32(As[buf][m * 12 + 4 + gc],       ahi[mi][2], alo[mi][2]);
            split_tf32(As[buf][(m + 8) * 12 + 4 + gc], ahi[mi][3], alo[mi][3]);
        }
#pragma unroll
        for (int ni = 0; ni < 8; ni++) {
            int n = wn + ni * 8 + gr;
            unsigned bh0, bl0, bh1, bl1;
            split_tf32(Bs[buf][n * 12 + gc],     bh0, bl0);
            split_tf32(Bs[buf][n * 12 + 4 + gc], bh1, bl1);
#pragma unroll
            for (int mi = 0; mi < 2; mi++) {
                MMA_TF32(acc[mi][ni], ahi[mi], bh0, bh1);
                MMA_TF32(acc[mi][ni], ahi[mi], bl0, bl1);
                MMA_TF32(acc[mi][ni], alo[mi], bh0, bh1);
            }
        }
        if (has) {
            const int nb = buf ^ 1;
            *(float4*)(As[nb] + a_row * 12 + a_k) = a4;
            Bs[nb][(b_n + 0) * 12 + b_k] = b4.x;
            Bs[nb][(b_n + 1) * 12 + b_k] = b4.y;
            Bs[nb][(b_n + 2) * 12 + b_k] = b4.z;
            Bs[nb][(b_n + 3) * 12 + b_k] = b4.w;
            __syncthreads();
            buf = nb;
        }
    }

#pragma unroll
    for (int mi = 0; mi < 2; mi++)
#pragma unroll
        for (int ni = 0; ni < 8; ni++) {
            int row = row0 + wm + mi * 16 + gr;
            int col = col0 + wn + ni * 8 + gc * 2;
            float bx = 0.f, by = 0.f;
            if (bias) { bx = bias[col]; by = bias[col + 1]; }
            float2 v0 = { acc[mi][ni][0] + bx, acc[mi][ni][1] + by };
            *(float2*)(C + (size_t)row * ldc + col) = v0;
            float2 v1 = { acc[mi][ni][2] + bx, acc[mi][ni][3] + by };
            *(float2*)(C + (size_t)(row + 8) * ldc + col) = v1;
        }
}

// ---------------------------------------------------------------------------
// FUSED projections: blocks 0-255 Q-proj (fp32), 256-511 K-proj (fp32),
// 512-767 V-proj (3xTF32).  (unchanged from R15 best)
// ---------------------------------------------------------------------------
__global__ void __launch_bounds__(256) proj_fused(
    const float* __restrict__ x, const float* __restrict__ ctx,
    const float* __restrict__ Wq, const float* __restrict__ Wkv,
    float* __restrict__ Q, float* __restrict__ KV)
{
    extern __shared__ float dsm[];
    const int bid = blockIdx.x;
    if (bid < 256) {
        sgemm_body(dsm, bid & 3, bid >> 2, x, Wq, Q, DQ, DQ, INNER, INNER);
    } else if (bid < 512) {
        int t = bid - 256;
        sgemm_body(dsm, t & 3, t >> 2, ctx, Wkv, KV, DQ, DQ, 2 * INNER, 2 * INNER);
    } else {
        int t = bid - 512;
        tf32gemm_body(dsm, t & 3, t >> 2, ctx, Wkv + INNER, nullptr, KV + INNER,
                      DQ, DQ, 2 * INNER, 2 * INNER);
    }
}

// ---------------------------------------------------------------------------
// sim via 3-term TF32 MMA (NT): S = 0.125 * Q_h . K_h^T   (unchanged R12 best)
// ---------------------------------------------------------------------------
__global__ void __launch_bounds__(512, 2) sim_tf32(
    const float* __restrict__ Q, const float* __restrict__ KV, float* __restrict__ S)
{
    extern __shared__ float sm[];
    float* Qs = sm;              // [128][68]
    float* Ks = sm + 128 * 68;   // [128][68]
    const int bh = blockIdx.z, b = bh >> 3, h = bh & 7;
    const int i0 = blockIdx.y * 128, j0 = blockIdx.x * 128;
    const int tid = threadIdx.x;

#pragma unroll
    for (int l = 0; l < 4; l++) {
        int idx = tid + l * 512;                 // 0..2047
        int row = idx >> 4, k0 = (idx & 15) * 4;
        float4 q4 = *(const float4*)(Q  + (size_t)(b * NQ + i0 + row) * INNER       + h * HD + k0);
        *(float4*)(Qs + row * 68 + k0) = q4;
        float4 k4 = *(const float4*)(KV + (size_t)(b * NK + j0 + row) * (2 * INNER) + h * HD + k0);
        *(float4*)(Ks + row * 68 + k0) = k4;
    }
    __syncthreads();

    const int lane = tid & 31, wid = tid >> 5;   // wid 0..15
    const int wm = (wid & 3) * 32, wn = (wid >> 2) * 32;
    const int gr = lane >> 2, gc = lane & 3;

    float acc[2][4][4];
#pragma unroll
    for (int mi = 0; mi < 2; mi++)
#pragma unroll
        for (int ni = 0; ni < 4; ni++)
#pragma unroll
            for (int q = 0; q < 4; q++) acc[mi][ni][q] = 0.f;

#pragma unroll
    for (int k0 = 0; k0 < 64; k0 += 8) {
        unsigned ahi[2][4], alo[2][4];
#pragma unroll
        for (int mi = 0; mi < 2; mi++) {
            int m = wm + mi * 16 + gr;
            split_tf32(Qs[m * 68 + k0 + gc],           ahi[mi][0], alo[mi][0]);
            split_tf32(Qs[(m + 8) * 68 + k0 + gc],     ahi[mi][1], alo[mi][1]);
            split_tf32(Qs[m * 68 + k0 + 4 + gc],       ahi[mi][2], alo[mi][2]);
            split_tf32(Qs[(m + 8) * 68 + k0 + 4 + gc], ahi[mi][3], alo[mi][3]);
        }
#pragma unroll
        for (int ni = 0; ni < 4; ni++) {
            int n = wn + ni * 8 + gr;
            unsigned bh0, bl0, bh1, bl1;
            split_tf32(Ks[n * 68 + k0 + gc],     bh0, bl0);
            split_tf32(Ks[n * 68 + k0 + 4 + gc], bh1, bl1);
#pragma unroll
            for (int mi = 0; mi < 2; mi++) {
                MMA_TF32(acc[mi][ni], ahi[mi], bh0, bh1);
                MMA_TF32(acc[mi][ni], ahi[mi], bl0, bl1);
                MMA_TF32(acc[mi][ni], alo[mi], bh0, bh1);
            }
        }
    }

    const float scale = 0.125f;
#pragma unroll
    for (int mi = 0; mi < 2; mi++)
#pragma unroll
        for (int ni = 0; ni < 4; ni++) {
            int row = i0 + wm + mi * 16 + gr;
            int col = j0 + wn + ni * 8 + gc * 2;
            float2 v0 = { acc[mi][ni][0] * scale, acc[mi][ni][1] * scale };
            __stcs((float2*)(S + ((size_t)bh * NQ + row) * NK + col), v0);
            float2 v1 = { acc[mi][ni][2] * scale, acc[mi][ni][3] * scale };
            __stcs((float2*)(S + ((size_t)bh * NQ + row + 8) * NK + col), v1);
        }
}

// ---------------------------------------------------------------------------
// out-projection, 512 threads / 16 warps / 32x32 warp tiles / 2 blocks/SM.
// Per-output k-order and 3-term order identical to the 256-thread version
// -> bitwise-identical output.  C = A @ Wout + bias,  A[8192,512], C[8192,1024].
// ---------------------------------------------------------------------------
__global__ void __launch_bounds__(512, 2) out_tf32(
    const float* __restrict__ A, const float* __restrict__ Bm,
    const float* __restrict__ bias, float* __restrict__ C)
{
    extern __shared__ float dsm[];
    float (*As)[128 * 12] = (float (*)[128 * 12])dsm;
    float (*Bs)[128 * 12] = (float (*)[128 * 12])(dsm + 2 * 128 * 12);
    const int tid  = threadIdx.x;
    const int row0 = blockIdx.y * 128, col0 = blockIdx.x * 128;
    // loads: 512 threads, float2 each (A tile 128x8, B tile 8x128)
    const int a_row = tid >> 2, a_k = (tid & 3) * 2;
    const int b_k   = tid >> 6, b_n = (tid & 63) * 2;
    const float* Ap = A  + (size_t)(row0 + a_row) * INNER + a_k;
    const float* Bp = Bm + (size_t)b_k * DQ + col0 + b_n;

    {
        float2 a2 = *(const float2*)Ap;
        As[0][a_row * 12 + a_k]     = a2.x;
        As[0][a_row * 12 + a_k + 1] = a2.y;
        float2 b2 = *(const float2*)Bp;
        Bs[0][(b_n + 0) * 12 + b_k] = b2.x;
        Bs[0][(b_n + 1) * 12 + b_k] = b2.y;
    }
    __syncthreads();

    const int lane = tid & 31, wid = tid >> 5;    // wid 0..15
    const int wm = (wid & 3) * 32, wn = (wid >> 2) * 32;
    const int gr = lane >> 2, gc = lane & 3;

    float acc[2][4][4];
#pragma unroll
    for (int mi = 0; mi < 2; mi++)
#pragma unroll
        for (int ni = 0; ni < 4; ni++)
#pragma unroll
            for (int q = 0; q < 4; q++) acc[mi][ni][q] = 0.f;

    int buf = 0;
    for (int k0 = 8; k0 <= INNER; k0 += 8) {
        const bool has = (k0 < INNER);
        float2 a2, b2;
        if (has) {
            a2 = *(const float2*)(Ap + k0);
            b2 = *(const float2*)(Bp + (size_t)k0 * DQ);
        }
        unsigned ahi[2][4], alo[2][4];
#pragma unroll
        for (int mi = 0; mi < 2; mi++) {
            int m = wm + mi * 16 + gr;
            split_tf32(As[buf][m * 12 + gc],           ahi[mi][0], alo[mi][0]);
            split_tf32(As[buf][(m + 8) * 12 + gc],     ahi[mi][1], alo[mi][1]);
            split_tf32(As[buf][m * 12 + 4 + gc],       ahi[mi][2], alo[mi][2]);
            split_tf32(As[buf][(m + 8) * 12 + 4 + gc], ahi[mi][3], alo[mi][3]);
        }
#pragma unroll
        for (int ni = 0; ni < 4; ni++) {
            int n = wn + ni * 8 + gr;
            unsigned bh0, bl0, bh1, bl1;
            split_tf32(Bs[buf][n * 12 + gc],     bh0, bl0);
            split_tf32(Bs[buf][n * 12 + 4 + gc], bh1, bl1);
#pragma unroll
            for (int mi = 0; mi < 2; mi++) {
                MMA_TF32(acc[mi][ni], ahi[mi], bh0, bh1);
                MMA_TF32(acc[mi][ni], ahi[mi], bl0, bl1);
                MMA_TF32(acc[mi][ni], alo[mi], bh0, bh1);
            }
        }
        if (has) {
            const int nb = buf ^ 1;
            As[nb][a_row * 12 + a_k]     = a2.x;
            As[nb][a_row * 12 + a_k + 1] = a2.y;
            Bs[nb][(b_n + 0) * 12 + b_k] = b2.x;
            Bs[nb][(b_n + 1) * 12 + b_k] = b2.y;
            __syncthreads();
            buf = nb;
        }
    }

#pragma unroll
    for (int mi = 0; mi < 2; mi++)
#pragma unroll
        for (int ni = 0; ni < 4; ni++) {
            int row = row0 + wm + mi * 16 + gr;
            int col = col0 + wn + ni * 8 + gc * 2;
            float bx = bias[col], by = bias[col + 1];
            float2 v0 = { acc[mi][ni][0] + bx, acc[mi][ni][1] + by };
            *(float2*)(C + (size_t)row * DQ + col) = v0;
            float2 v1 = { acc[mi][ni][2] + bx, acc[mi][ni][3] + by };
            *(float2*)(C + (size_t)(row + 8) * DQ + col) = v1;
        }
}

// ---------------------------------------------------------------------------
// topk v2 (unchanged from R13 best): 2 rows per 256-thread block; exact top-64
// (bitonic warp threshold prefilter, scan compaction, rank-select composite
// keys == jax.lax.top_k ties), softmax, vectorized sparse PV.
// ---------------------------------------------------------------------------
__global__ void __launch_bounds__(256, 7) topk_attn(
    const float* __restrict__ S, const float* __restrict__ KV, float* __restrict__ O)
{
    __shared__ __align__(16) unsigned long long ckey[2][528];
    __shared__ float warpthr[2][4];
    __shared__ float selv[2][64];
    __shared__ int   seli[2][64];
    __shared__ float s_wsum[2];
    __shared__ int   s_ncand[2];
    __shared__ float w[2][64];
    __shared__ float part[2][4][64];

    const int tid  = threadIdx.x;
    const int sub  = tid >> 7;          // row within block (0/1)
    const int rtid = tid & 127;
    const int r  = blockIdx.x * 2 + sub;
    const int bh = r >> 11, i = r & 2047;
    const int b  = bh >> 3, h = bh & 7;
    const float* srow = S + (size_t)r * NK;

    const int lane = tid & 31, wrp = rtid >> 5;   // warp-in-row 0..3
    if (rtid == 0) s_ncand[sub] = 0;

    float vals[16];
#pragma unroll
    for (int t = 0; t < 4; t++) {
        float4 v = __ldcs((const float4*)srow + rtid + t * 128);
        vals[t * 4 + 0] = v.x; vals[t * 4 + 1] = v.y;
        vals[t * 4 + 2] = v.z; vals[t * 4 + 3] = v.w;
    }
    float tmax = vals[0];
#pragma unroll
    for (int t = 1; t < 16; t++) tmax = fmaxf(tmax, vals[t]);

    {
        float v = tmax;
#pragma unroll
        for (int k = 2; k <= 32; k <<= 1) {
#pragma unroll
            for (int j = k >> 1; j > 0; j >>= 1) {
                float o = __shfl_xor_sync(0xffffffffu, v, j);
                bool ascBlock = ((lane & k) != 0);
                bool upper    = ((lane & j) != 0);
                v = (upper == ascBlock) ? fmaxf(v, o) : fminf(v, o);
            }
        }
        float t_w = __shfl_sync(0xffffffffu, v, 15);   // 16th largest in warp
        if (lane == 0) warpthr[sub][wrp] = t_w;
    }
    __syncthreads();
    const float thr = fminf(fminf(warpthr[sub][0], warpthr[sub][1]),
                            fminf(warpthr[sub][2], warpthr[sub][3]));

    {
        int cnt = 0;
#pragma unroll
        for (int t = 0; t < 16; t++) cnt += (vals[t] >= thr) ? 1 : 0;
        int pfx = cnt;
#pragma unroll
        for (int off = 1; off < 32; off <<= 1) {
            int o = __shfl_up_sync(0xffffffffu, pfx, off);
            if (lane >= off) pfx += o;
        }
        int wbase = 0;
        if (lane == 31) wbase = atomicAdd(&s_ncand[sub], pfx);
        wbase = __shfl_sync(0xffffffffu, wbase, 31);
        int p = wbase + pfx - cnt;
#pragma unroll
        for (int t = 0; t < 16; t++) {
            if (vals[t] >= thr) {
                if (p < CCAP) {
                    int j = (rtid + (t >> 2) * 128) * 4 + (t & 3);
                    ckey[sub][p] =
                        ((unsigned long long)fkey(vals[t]) << 32) | (unsigned)(2047 - j);
                }
                p++;
            }
        }
    }
    __syncthreads();
    const int nc = (s_ncand[sub] < CCAP) ? s_ncand[sub] : CCAP;
    if (rtid == 0) ckey[sub][nc] = 0ull;
    __syncthreads();

    for (int c = rtid; c < nc; c += 128) {
        unsigned long long k = ckey[sub][c];
        int rk = 0;
        for (int o = 0; o < nc; o += 2) {
            ulonglong2 kk = *(const ulonglong2*)&ckey[sub][o];
            rk += (kk.x > k) + (kk.y > k);
        }
        if (rk < KKEEP) {
            selv[sub][rk] = unfkey((unsigned)(k >> 32));
            seli[sub][rk] = 2047 - (int)(k & 0xffffffffu);
        }
    }
    __syncthreads();   // selv[sub][0] = row max

    if (rtid < 64) w[sub][rtid] = expf(selv[sub][rtid] - selv[sub][0]);
    __syncthreads();
    if (rtid < 32) {
        float s = w[sub][rtid] + w[sub][rtid + 32];
#pragma unroll
        for (int off = 16; off; off >>= 1)
            s += __shfl_xor_sync(0xffffffffu, s, off);
        if (rtid == 0) s_wsum[sub] = s;
    }
    __syncthreads();

    {
        const int kg = rtid >> 4;            // 0..7 (8 keys each)
        const int ln = rtid & 15;            // float4 lane
        const float* Vb = KV + (size_t)b * NK * (2 * INNER) + INNER + h * HD + ln * 4;
        float4 a4 = make_float4(0.f, 0.f, 0.f, 0.f);
#pragma unroll
        for (int k = 0; k < 8; k++) {
            int idx = kg * 8 + k;
            float wk = w[sub][idx];
            float4 v4 = *(const float4*)(Vb + (size_t)seli[sub][idx] * (2 * INNER));
            a4.x += wk * v4.x; a4.y += wk * v4.y;
            a4.z += wk * v4.z; a4.w += wk * v4.w;
        }
        a4.x += __shfl_down_sync(0xffffffffu, a4.x, 16);
        a4.y += __shfl_down_sync(0xffffffffu, a4.y, 16);
        a4.z += __shfl_down_sync(0xffffffffu, a4.z, 16);
        a4.w += __shfl_down_sync(0xffffffffu, a4.w, 16);
        if (lane < 16)
            *(float4*)&part[sub][wrp][ln * 4] = a4;
    }
    __syncthreads();
    if (rtid < 64) {
        const int d = rtid;
        float o = (part[sub][0][d] + part[sub][1][d]) +
                  (part[sub][2][d] + part[sub][3][d]);
        o /= s_wsum[sub];
        O[((size_t)(b * NQ + i)) * INNER + h * HD + d] = o;
    }
}

// ---------------------------------------------------------------------------
extern "C" void kernel_launch(void* const* d_in, const int* in_sizes, int n_in,
                              void* d_out, int out_size)
{
    const float* x    = (const float*)d_in[0];
    const float* ctx  = (const float*)d_in[1];
    const float* Wq   = (const float*)d_in[2];
    const float* Wkv  = (const float*)d_in[3];
    const float* Wout = (const float*)d_in[4];
    const float* bout = (const float*)d_in[5];
    float* out = (float*)d_out;

    float *pQ, *pKV, *pS, *pO;
    cudaGetSymbolAddress((void**)&pQ,  g_Q);
    cudaGetSymbolAddress((void**)&pKV, g_KV);
    cudaGetSymbolAddress((void**)&pS,  g_S);
    cudaGetSymbolAddress((void**)&pO,  g_O);

    const int simSmem  = 2 * 128 * 68 * sizeof(float);     // 69632 B
    const int projSmem = 2 * 2 * 128 * 12 * sizeof(float); // 24576 B
    cudaFuncSetAttribute(sim_tf32, cudaFuncAttributeMaxDynamicSharedMemorySize, simSmem);

    // FUSED Q/K/V projections (pipe-overlapped; bitwise-identical math)
    proj_fused<<<dim3(768), dim3(256), projSmem>>>(x, ctx, Wq, Wkv, pQ, pKV);
    // sim = Q @ K^T * scale (3-term TF32; 512 threads, 2 blocks/SM)
    sim_tf32<<<dim3(NK / 128, NQ / 128, BATCH * NH), dim3(512), simSmem>>>(pQ, pKV, pS);
    // exact top-64 + softmax + sparse PV (2 rows per block)
    topk_attn<<<dim3(BATCH * NH * NQ / 2), dim3(256)>>>(pS, pKV, pO);
    // out = O @ Wout + bout (3xTF32; 512 threads, 2 blocks/SM)
    out_tf32<<<dim3(DQ / 128, BATCH * NQ / 128), dim3(512), projSmem>>>(
        pO, Wout, bout, out);
}